// round 14
// baseline (speedup 1.0000x reference)
#include <cuda_runtime.h>
#include <cuda_fp8.h>
#include <cuda_fp16.h>
#include <math.h>

#define B_    2
#define L_    2048
#define H_    16
#define D_    128
#define BH_   (B_*H_)      // 32
#define NQB   16
#define NKB   32
#define TOPK  16
#define SCALE_ 0.08838834764831845f   // 1/sqrt(128)
#define L2E_   1.4426950408889634f
#define FP8MAX_ (448.0f/2.25f)

// ---------------- scratch (device globals; no runtime allocation) ----------------
__device__ int    g_q8[BH_*L_*32];            // int8 packed, [bh][l][d/4]
__device__ int    g_k8[BH_*L_*32];
__device__ float  g_qsc[BH_*NQB];
__device__ float  g_ksc[BH_*NKB];
__device__ __half g_v16[(size_t)BH_*L_*D_];   // raw fp8 values as fp16, [bh][l][d]
__device__ float  g_qp[BH_*NQB*D_];
__device__ float  g_kp[BH_*NKB*D_];
__device__ float  g_vspart[BH_*16*D_];
__device__ float  g_vs[BH_*D_];
__device__ float  g_wflag[1];
// linear-branch scratch (dead unless proj_w != 0)
__device__ float g_qf[BH_*L_*D_];
__device__ float g_kf[BH_*L_*D_];
__device__ float g_ksum[BH_*D_];
__device__ float g_kvsum[BH_*D_*D_];
__device__ float g_G[BH_*D_*D_];

// ---------------- helpers ----------------
__device__ __forceinline__ void cpasync16(unsigned s, const void* g) {
    asm volatile("cp.async.cg.shared.global [%0], [%1], 16;\n" :: "r"(s), "l"(g));
}
#define CP_COMMIT() asm volatile("cp.async.commit_group;\n" ::: "memory")
#define CP_WAIT1()  asm volatile("cp.async.wait_group 1;\n" ::: "memory")
#define CP_WAIT2()  asm volatile("cp.async.wait_group 2;\n" ::: "memory")

__device__ __forceinline__ void ldsm4(unsigned& r0, unsigned& r1, unsigned& r2, unsigned& r3,
                                      unsigned a) {
    asm volatile("ldmatrix.sync.aligned.m8n8.x4.shared.b16 {%0,%1,%2,%3}, [%4];"
                 : "=r"(r0), "=r"(r1), "=r"(r2), "=r"(r3) : "r"(a));
}
__device__ __forceinline__ void ldsm4t(unsigned& r0, unsigned& r1, unsigned& r2, unsigned& r3,
                                       unsigned a) {
    asm volatile("ldmatrix.sync.aligned.m8n8.x4.trans.shared.b16 {%0,%1,%2,%3}, [%4];"
                 : "=r"(r0), "=r"(r1), "=r"(r2), "=r"(r3) : "r"(a));
}
__device__ __forceinline__ void imma16832(int& c0, int& c1, int& c2, int& c3,
                                          unsigned a0, unsigned a1, unsigned a2, unsigned a3,
                                          unsigned b0, unsigned b1) {
    asm volatile("mma.sync.aligned.m16n8k32.row.col.s32.s8.s8.s32 "
                 "{%0,%1,%2,%3}, {%4,%5,%6,%7}, {%8,%9}, {%0,%1,%2,%3};"
                 : "+r"(c0), "+r"(c1), "+r"(c2), "+r"(c3)
                 : "r"(a0), "r"(a1), "r"(a2), "r"(a3), "r"(b0), "r"(b1));
}
__device__ __forceinline__ void hmma16816(float& d0, float& d1, float& d2, float& d3,
                                          unsigned a0, unsigned a1, unsigned a2, unsigned a3,
                                          unsigned b0, unsigned b1) {
    asm volatile("mma.sync.aligned.m16n8k16.row.col.f32.f16.f16.f32 "
                 "{%0,%1,%2,%3}, {%4,%5,%6,%7}, {%8,%9}, {%0,%1,%2,%3};"
                 : "+f"(d0), "+f"(d1), "+f"(d2), "+f"(d3)
                 : "r"(a0), "r"(a1), "r"(a2), "r"(a3), "r"(b0), "r"(b1));
}
__device__ __forceinline__ float ex2f(float x) {
    float r;
    asm("ex2.approx.f32 %0, %1;" : "=f"(r) : "f"(x));
    return r;
}

// round-to-nearest-even + saturating s8 pack of 4 scaled floats
__device__ __forceinline__ unsigned quantpack(float4 x, float inv) {
    int i0, i1, i2, i3;
    asm("cvt.rni.s32.f32 %0, %1;" : "=r"(i0) : "f"(x.x*inv));
    asm("cvt.rni.s32.f32 %0, %1;" : "=r"(i1) : "f"(x.y*inv));
    asm("cvt.rni.s32.f32 %0, %1;" : "=r"(i2) : "f"(x.z*inv));
    asm("cvt.rni.s32.f32 %0, %1;" : "=r"(i3) : "f"(x.w*inv));
    unsigned t, r;
    asm("cvt.pack.sat.s8.s32.b32 %0, %1, %2, %3;" : "=r"(t) : "r"(i3), "r"(i2), "r"(0u));
    asm("cvt.pack.sat.s8.s32.b32 %0, %1, %2, %3;" : "=r"(r) : "r"(i1), "r"(i0), "r"(t));
    return r;
}

// fp8-e4m3 satfinite roundtrip of 2 floats, result as packed half2 (low = x0)
__device__ __forceinline__ unsigned cvt2_fp8_f16(float x0, float x1) {
    unsigned short u;
    asm("cvt.rn.satfinite.e4m3x2.f32 %0, %1, %2;" : "=h"(u) : "f"(x1), "f"(x0));
    unsigned r;
    asm("cvt.rn.f16x2.e4m3x2 %0, %1;" : "=r"(r) : "h"(u));
    return r;
}

// ---------------- preproc1: fused_q | pool_k | vscale_part | wflag ----------------
__global__ void preproc1_kernel(const float* __restrict__ q, const float* __restrict__ k,
                                const float* __restrict__ v, const float* __restrict__ w) {
    __shared__ float red[256];
    __shared__ float sca[2];
    int tid = threadIdx.x;
    unsigned bx = blockIdx.x;
    if (bx < 512) {
        int bh = bx >> 4, qb = bx & 15;
        int b = bh >> 4, h = bh & 15;
        int d = tid & 127, half = tid >> 7;
        const float* base = q + ((size_t)(b*L_ + qb*128 + half*64)*H_ + h)*D_ + d;
        float s = 0.f, mx = 0.f;
#pragma unroll 8
        for (int r = 0; r < 64; r++) {
            float x = base[(size_t)r*H_*D_];
            s += x; mx = fmaxf(mx, fabsf(x));
        }
        red[tid] = mx; __syncthreads();
        for (int st = 128; st > 0; st >>= 1) { if (tid < st) red[tid] = fmaxf(red[tid], red[tid+st]); __syncthreads(); }
        if (tid == 0) { float sc = red[0]/127.f + 1e-8f; sca[0] = sc; sca[1] = 1.f/sc; g_qsc[bh*NQB + qb] = sc; }
        __syncthreads();
        red[tid] = s; __syncthreads();
        if (half == 0) g_qp[(bh*NQB + qb)*D_ + d] = (red[d] + red[d+128]) * (1.f/128.f);
        float inv = sca[1];
        for (int i4 = tid; i4 < 128*32; i4 += 256) {
            int r = i4 >> 5, c = i4 & 31;
            float4 x = *(const float4*)&q[((size_t)(b*L_ + qb*128 + r)*H_ + h)*D_ + 4*c];
            g_q8[(bh*L_ + qb*128 + r)*32 + c] = quantpack(x, inv);
        }
    } else if (bx < 1536) {
        int i = bx - 512;
        int bh = i >> 5, kb = i & 31;
        int b = bh >> 4, h = bh & 15;
        int d = tid & 127, half = tid >> 7;
        const float* base = k + ((size_t)(b*L_ + kb*64 + half*32)*H_ + h)*D_ + d;
        float s = 0.f;
#pragma unroll 8
        for (int r = 0; r < 32; r++) s += base[(size_t)r*H_*D_];
        red[tid] = s; __syncthreads();
        if (half == 0) g_kp[(bh*NKB + kb)*D_ + d] = (red[d] + red[d+128]) * (1.f/64.f);
    } else if (bx < 2048) {
        int i = bx - 1536;
        int bh = i >> 4, ch = i & 15;
        int b = bh >> 4, h = bh & 15;
        int d = tid & 127, half = tid >> 7;
        const float* base = v + ((size_t)(b*L_ + ch*128 + half*64)*H_ + h)*D_ + d;
        float mx = 0.f;
#pragma unroll 8
        for (int r = 0; r < 64; r++) mx = fmaxf(mx, fabsf(base[(size_t)r*H_*D_]));
        red[tid] = mx; __syncthreads();
        if (half == 0) g_vspart[(bh*16 + ch)*D_ + d] = fmaxf(red[d], red[d+128]);
    } else {
        float s = 0.f;
        for (int i = tid; i < D_*D_; i += 256) s += fabsf(w[i]);
        red[tid] = s; __syncthreads();
        for (int st = 128; st > 0; st >>= 1) { if (tid < st) red[tid] += red[tid+st]; __syncthreads(); }
        if (tid == 0) g_wflag[0] = red[0];
    }
}

// ---------------- preproc2: quant_k (km inline) | vdeq (fp8->fp16 stream) ----------
__global__ void preproc2_kernel(const float* __restrict__ k, const float* __restrict__ v) {
    __shared__ float red[256];
    __shared__ float svec[128];
    __shared__ float sca[2];
    int tid = threadIdx.x;
    unsigned bx = blockIdx.x;
    if (bx < 1024) {
        int bh = bx >> 5, kb = bx & 31;
        int b = bh >> 4, h = bh & 15;
        if (tid < 128) {
            float s = 0.f;
#pragma unroll
            for (int j = 0; j < NKB; j++) s += g_kp[(bh*NKB + j)*D_ + tid];
            svec[tid] = s * (1.f/NKB);
        }
        __syncthreads();
        int d = tid & 127, half = tid >> 7;
        const float* base = k + ((size_t)(b*L_ + kb*64 + half*32)*H_ + h)*D_ + d;
        float km = svec[d];
        float mx = 0.f;
#pragma unroll 8
        for (int r = 0; r < 32; r++) mx = fmaxf(mx, fabsf(base[(size_t)r*H_*D_] - km));
        red[tid] = mx; __syncthreads();
        for (int st = 128; st > 0; st >>= 1) { if (tid < st) red[tid] = fmaxf(red[tid], red[tid+st]); __syncthreads(); }
        if (tid == 0) { float sc = red[0]/127.f + 1e-8f; g_ksc[bh*NKB + kb] = sc; sca[1] = 1.f/sc; }
        __syncthreads();
        float inv = sca[1];
        for (int i4 = tid; i4 < 64*32; i4 += 256) {
            int r = i4 >> 5, c = i4 & 31;
            float4 x = *(const float4*)&k[((size_t)(b*L_ + kb*64 + r)*H_ + h)*D_ + 4*c];
            x.x -= svec[4*c+0]; x.y -= svec[4*c+1]; x.z -= svec[4*c+2]; x.w -= svec[4*c+3];
            g_k8[(bh*L_ + kb*64 + r)*32 + c] = quantpack(x, inv);
        }
    } else {
        int i = bx - 1024;
        int bh = i >> 4, lc = i & 15;
        int b = bh >> 4, h = bh & 15;
        if (tid < 128) {
            float mx = 0.f;
#pragma unroll
            for (int ch = 0; ch < 16; ch++) mx = fmaxf(mx, g_vspart[(bh*16 + ch)*D_ + tid]);
            float s = mx/FP8MAX_ + 1e-8f;
            g_vs[bh*D_ + tid] = s;            // idempotent across lc blocks
            svec[tid] = 1.f/s;
        }
        __syncthreads();
        int l0 = lc*128;
        for (int i4 = tid; i4 < 128*32; i4 += 256) {
            int r = i4 >> 5, d4 = (i4 & 31) << 2;
            float4 x = *(const float4*)&v[((size_t)(b*L_ + l0 + r)*H_ + h)*D_ + d4];
            uint2 u;
            u.x = cvt2_fp8_f16(x.x*svec[d4+0], x.y*svec[d4+1]);
            u.y = cvt2_fp8_f16(x.z*svec[d4+2], x.w*svec[d4+3]);
            *(uint2*)(g_v16 + ((size_t)(bh*L_ + l0 + r))*D_ + d4) = u;
        }
    }
}

// ---------------- flash block-sparse attention: pipelined IMMA S + HMMA PV ------
// smem: [0..1023] sim(32f)+sel(16i) | sQ 128x144B | sK[3] 64x144B | sV[3] 64x272B
#define SQ_OFF  1024
#define SK_OFF(st) (19456 + (st)*9216)
#define SV_OFF(st) (47104 + (st)*17408)
#define SMEM_BYTES 99328

__global__ void __launch_bounds__(256, 2) attn_kernel(float* __restrict__ out,
                                                      const float* __restrict__ pb) {
    extern __shared__ char sm[];
    unsigned sbase = (unsigned)__cvta_generic_to_shared(sm);
    float* simS = (float*)sm;
    int*   selS = (int*)(sm + 128);

    int bh = blockIdx.x >> 4, qb = blockIdx.x & 15;
    int b = bh >> 4, h = bh & 15;
    int tid = threadIdx.x;
    int w = tid >> 5, lane = tid & 31;
    int g = lane >> 2, tig = lane & 3;
    int lr = lane & 7, lm = lane >> 3;

    unsigned qmat = sbase + SQ_OFF + (unsigned)((16*w + 8*(lm & 1) + lr)*144 + 16*(lm >> 1));
    unsigned bmat = (unsigned)((8*(lm >> 1) + lr)*144 + 16*(lm & 1));
    unsigned vmat = (unsigned)(((lm & 1)*8 + lr)*272 + (lm >> 1)*16);

    float qs = g_qsc[bh*NQB + qb];
    const float* kscp = g_ksc + bh*NKB;

    // ---- group: Q prefetch (overlaps with sim/topk) ----
    {
        const char* qg = (const char*)(g_q8 + (bh*L_ + qb*128)*32);
        for (int c = tid; c < 1024; c += 256) {
            int r = c >> 3, c8 = c & 7;
            cpasync16(sbase + SQ_OFF + r*144 + c8*16, qg + r*128 + c8*16);
        }
        CP_COMMIT();
    }

    // ---- inline block-similarity + stable top-k ----
    {
        int ki = tid >> 3, part = tid & 7;
        const float* qp = g_qp + (bh*NQB + qb)*D_;
        const float* kp = g_kp + (bh*NKB + ki)*D_;
        int d0 = part*16;
        float s = 0.f;
#pragma unroll
        for (int j = 0; j < 16; j++) s += qp[d0+j]*kp[d0+j];
        s += __shfl_xor_sync(0xffffffffu, s, 1);
        s += __shfl_xor_sync(0xffffffffu, s, 2);
        s += __shfl_xor_sync(0xffffffffu, s, 4);
        if (part == 0) simS[ki] = s;
    }
    __syncthreads();
    if (tid < 32) {
        float sj = simS[tid];
        int rank = 0;
#pragma unroll
        for (int i = 0; i < 32; i++)
            rank += (simS[i] > sj) || (simS[i] == sj && i < tid);
        if (rank < TOPK) selS[rank] = tid;
    }
    __syncthreads();

    // ---- pipeline prologue groups: {K0}, {K1,V0}, {K2,V1} ----
    {
        int kb = selS[0];
        const char* kg = (const char*)(g_k8 + (bh*L_ + kb*64)*32);
        for (int c = tid; c < 512; c += 256) {
            int r = c >> 3, c8 = c & 7;
            cpasync16(sbase + SK_OFF(0) + r*144 + c8*16, kg + r*128 + c8*16);
        }
        CP_COMMIT();
    }
#pragma unroll
    for (int ps = 0; ps < 2; ps++) {
        int kbk = selS[ps+1];
        const char* kg = (const char*)(g_k8 + (bh*L_ + kbk*64)*32);
        for (int c = tid; c < 512; c += 256) {
            int r = c >> 3, c8 = c & 7;
            cpasync16(sbase + SK_OFF(ps+1) + r*144 + c8*16, kg + r*128 + c8*16);
        }
        int kbv = selS[ps];
        for (int c = tid; c < 1024; c += 256) {
            int r = c >> 4, c16 = c & 15;
            cpasync16(sbase + SV_OFF(ps) + r*272 + c16*16,
                      (const char*)(g_v16 + ((size_t)(bh*L_ + kbv*64 + r))*D_) + c16*16);
        }
        CP_COMMIT();
    }

    // ---- wait {Q, K0}; issue IMMA S_0 ----
    int c[8][4];
#pragma unroll
    for (int nt = 0; nt < 8; nt++)
#pragma unroll
        for (int e = 0; e < 4; e++) c[nt][e] = 0;

    CP_WAIT2();
    __syncthreads();
    {
        unsigned skb0 = sbase + SK_OFF(0) + bmat;
#pragma unroll
        for (int ks = 0; ks < 4; ks++) {
            unsigned a0, a1, a2, a3;
            ldsm4(a0, a1, a2, a3, qmat + 32*ks);
#pragma unroll
            for (int p = 0; p < 4; p++) {
                unsigned b0, b1, b2, b3;
                ldsm4(b0, b1, b2, b3, skb0 + p*2304 + 32*ks);
                imma16832(c[2*p][0], c[2*p][1], c[2*p][2], c[2*p][3],
                          a0, a1, a2, a3, b0, b1);
                imma16832(c[2*p+1][0], c[2*p+1][1], c[2*p+1][2], c[2*p+1][3],
                          a0, a1, a2, a3, b2, b3);
            }
        }
    }

    float o[16][4];
    float m0 = -INFINITY, m1 = -INFINITY, l0 = 0.f, l1 = 0.f;
#pragma unroll
    for (int dt = 0; dt < 16; dt++)
#pragma unroll
        for (int e = 0; e < 4; e++) o[dt][e] = 0.f;

#pragma unroll 1
    for (int s = 0; s < TOPK; s++) {
        CP_WAIT1();
        __syncthreads();          // groups ≤ s complete: K_{s+1}, V_s resident

        // prefetch group {K_{s+3}, V_{s+2}}
        if (s < TOPK-3) {
            int kbn = selS[s+3];
            const char* kg = (const char*)(g_k8 + (bh*L_ + kbn*64)*32);
            int slot = (s+3) % 3;
            for (int cc = tid; cc < 512; cc += 256) {
                int r = cc >> 3, c8 = cc & 7;
                cpasync16(sbase + SK_OFF(slot) + r*144 + c8*16, kg + r*128 + c8*16);
            }
        }
        if (s < TOPK-2) {
            int vbn = selS[s+2];
            int slot = (s+2) % 3;
            for (int cc = tid; cc < 1024; cc += 256) {
                int r = cc >> 4, c16 = cc & 15;
                cpasync16(sbase + SV_OFF(slot) + r*272 + c16*16,
                          (const char*)(g_v16 + ((size_t)(bh*L_ + vbn*64 + r))*D_) + c16*16);
            }
        }
        CP_COMMIT();

        float csc2 = qs * kscp[selS[s]] * (SCALE_ * L2E_);
        unsigned svb  = sbase + SV_OFF(s % 3) + vmat;
        unsigned skbn = sbase + SK_OFF((s+1) % 3) + bmat;
        bool more = (s + 1 < TOPK);

#pragma unroll
        for (int hh = 0; hh < 2; hh++) {
            // 1. consume this half's S (log2 domain)
            float sv[4][4];
#pragma unroll
            for (int nt4 = 0; nt4 < 4; nt4++)
#pragma unroll
                for (int e = 0; e < 4; e++)
                    sv[nt4][e] = (float)c[4*hh + nt4][e] * csc2;

            // 2. issue IMMA S_{s+1} for this half (overlaps softmax below)
            if (more) {
#pragma unroll
                for (int nt4 = 0; nt4 < 4; nt4++)
#pragma unroll
                    for (int e = 0; e < 4; e++) c[4*hh + nt4][e] = 0;
#pragma unroll
                for (int ks = 0; ks < 4; ks++) {
                    unsigned a0, a1, a2, a3;
                    ldsm4(a0, a1, a2, a3, qmat + 32*ks);
#pragma unroll
                    for (int pl = 0; pl < 2; pl++) {
                        int p = 2*hh + pl;
                        unsigned b0, b1, b2, b3;
                        ldsm4(b0, b1, b2, b3, skbn + p*2304 + 32*ks);
                        imma16832(c[2*p][0], c[2*p][1], c[2*p][2], c[2*p][3],
                                  a0, a1, a2, a3, b0, b1);
                        imma16832(c[2*p+1][0], c[2*p+1][1], c[2*p+1][2], c[2*p+1][3],
                                  a0, a1, a2, a3, b2, b3);
                    }
                }
            }

            // 3. online softmax for this 32-key half
            float mloc0 = -INFINITY, mloc1 = -INFINITY;
#pragma unroll
            for (int nt4 = 0; nt4 < 4; nt4++) {
                mloc0 = fmaxf(mloc0, fmaxf(sv[nt4][0], sv[nt4][1]));
                mloc1 = fmaxf(mloc1, fmaxf(sv[nt4][2], sv[nt4][3]));
            }
            mloc0 = fmaxf(mloc0, __shfl_xor_sync(0xffffffffu, mloc0, 1));
            mloc0 = fmaxf(mloc0, __shfl_xor_sync(0xffffffffu, mloc0, 2));
            mloc1 = fmaxf(mloc1, __shfl_xor_sync(0xffffffffu, mloc1, 1));
            mloc1 = fmaxf(mloc1, __shfl_xor_sync(0xffffffffu, mloc1, 2));
            float mn0 = fmaxf(m0, mloc0), mn1 = fmaxf(m1, mloc1);
            float corr0 = ex2f(m0 - mn0), corr1 = ex2f(m1 - mn1);
            m0 = mn0; m1 = mn1;

            unsigned phl0[4], phl1[4];
            float ps0 = 0.f, ps1 = 0.f;
#pragma unroll
            for (int nt4 = 0; nt4 < 4; nt4++) {
                float p00 = ex2f(sv[nt4][0] - mn0), p01 = ex2f(sv[nt4][1] - mn0);
                __half2 h0 = __floats2half2_rn(p00, p01);
                phl0[nt4] = *reinterpret_cast<unsigned*>(&h0);
                float2 f0 = __half22float2(h0);
                ps0 += f0.x + f0.y;
                float p10 = ex2f(sv[nt4][2] - mn1), p11 = ex2f(sv[nt4][3] - mn1);
                __half2 h1 = __floats2half2_rn(p10, p11);
                phl1[nt4] = *reinterpret_cast<unsigned*>(&h1);
                float2 f1 = __half22float2(h1);
                ps1 += f1.x + f1.y;
            }
            ps0 += __shfl_xor_sync(0xffffffffu, ps0, 1);
            ps0 += __shfl_xor_sync(0xffffffffu, ps0, 2);
            ps1 += __shfl_xor_sync(0xffffffffu, ps1, 1);
            ps1 += __shfl_xor_sync(0xffffffffu, ps1, 2);
            l0 = l0*corr0 + ps0;
            l1 = l1*corr1 + ps1;

#pragma unroll
            for (int dt = 0; dt < 16; dt++) {
                o[dt][0] *= corr0; o[dt][1] *= corr0;
                o[dt][2] *= corr1; o[dt][3] *= corr1;
            }

            // 4. O += P V for this half's 32 keys (kc = 2h, 2h+1)
#pragma unroll
            for (int kl = 0; kl < 2; kl++) {
                int kc = 2*hh + kl;
                unsigned pa0 = phl0[2*kl],   pa1 = phl1[2*kl];
                unsigned pa2 = phl0[2*kl+1], pa3 = phl1[2*kl+1];
#pragma unroll
                for (int p = 0; p < 8; p++) {
                    unsigned b0, b1, b2, b3;
                    ldsm4t(b0, b1, b2, b3, svb + kc*4352 + p*32);
                    hmma16816(o[2*p][0], o[2*p][1], o[2*p][2], o[2*p][3],
                              pa0, pa1, pa2, pa3, b0, b1);
                    hmma16816(o[2*p+1][0], o[2*p+1][1], o[2*p+1][2], o[2*p+1][3],
                              pa0, pa1, pa2, pa3, b2, b3);
                }
            }
        }
    }

    // ---- epilogue ----
    float inv0 = 1.f / l0, inv1 = 1.f / l1;
    int row0 = qb*128 + 16*w + g, row1 = row0 + 8;
    float* o0 = out + ((size_t)(b*L_ + row0)*H_ + h)*D_;
    float* o1 = out + ((size_t)(b*L_ + row1)*H_ + h)*D_;
    const float* vs = g_vs + bh*D_;
#pragma unroll
    for (int dt = 0; dt < 16; dt++) {
        int d0 = 8*dt + 2*tig;
        float2 vsc = *(const float2*)&vs[d0];
        float2 bb  = *(const float2*)&pb[d0];
        float2 r0, r1;
        r0.x = o[dt][0]*vsc.x*inv0 + bb.x;
        r0.y = o[dt][1]*vsc.y*inv0 + bb.y;
        r1.x = o[dt][2]*vsc.x*inv1 + bb.x;
        r1.y = o[dt][3]*vsc.y*inv1 + bb.y;
        *(float2*)&o0[d0] = r0;
        *(float2*)&o1[d0] = r1;
    }
}

// ---------------- linear branch, single guarded kernel (dead when proj_w == 0) --
__global__ void lin_dead_kernel(const float* __restrict__ q, const float* __restrict__ k,
                                const float* __restrict__ v, const float* __restrict__ w,
                                float* __restrict__ out) {
    if (g_wflag[0] == 0.f) return;
    int tid = threadIdx.x;
    for (int row = tid; row < 2*BH_*L_; row += 256) {
        int which = row >= BH_*L_;
        int rr = which ? row - BH_*L_ : row;
        int bh = rr / L_, l = rr % L_;
        int b = bh >> 4, h = bh & 15;
        const float* src = (which ? k : q) + ((size_t)(b*L_ + l)*H_ + h)*D_;
        float mx = -INFINITY;
        for (int d = 0; d < D_; d++) mx = fmaxf(mx, src[d]);
        float sum = 0.f;
        float* dst = (which ? g_kf : g_qf) + (size_t)(bh*L_ + l)*D_;
        for (int d = 0; d < D_; d++) { float e = __expf(src[d]-mx); dst[d] = e; sum += e; }
        float inv = 1.f/sum;
        for (int d = 0; d < D_; d++) dst[d] *= inv;
    }
    __syncthreads();
    for (int i = tid; i < BH_*D_; i += 256) {
        int bh = i >> 7;
        float s = 0.f;
        for (int l = 0; l < L_; l++) s += g_kf[(size_t)(bh*L_ + l)*D_ + (i & 127)];
        g_ksum[i] = s;
    }
    __syncthreads();
    for (int i = tid; i < BH_*D_*D_; i += 256) {
        int bh = i >> 14, rem = i & 16383, d = rem >> 7, e = rem & 127;
        int b = bh >> 4, h = bh & 15;
        float s = 0.f;
        for (int l = 0; l < L_; l++)
            s += g_kf[(size_t)(bh*L_ + l)*D_ + d] * v[((size_t)(b*L_ + l)*H_ + h)*D_ + e];
        g_kvsum[i] = s;
    }
    __syncthreads();
    for (int i = tid; i < BH_*D_*D_; i += 256) {
        int bh = i >> 14, rem = i & 16383, d = rem >> 7, e = rem & 127;
        float s = 0.f;
        for (int f = 0; f < D_; f++) s += g_kvsum[((size_t)bh*D_ + d)*D_ + f]*w[e*D_ + f];
        g_G[i] = s;
    }
    __syncthreads();
    for (int i = tid; i < BH_*L_; i += 256) {
        int bh = i / L_, l = i % L_;
        int b = bh >> 4, h = bh & 15;
        const float* qf = g_qf + (size_t)(bh*L_ + l)*D_;
        float pd = 0.f;
        for (int d = 0; d < D_; d++) pd += qf[d]*g_ksum[bh*D_ + d];
        float denom = 1e-5f + pd;
        for (int e = 0; e < D_; e++) {
            float s = 0.f;
            for (int d = 0; d < D_; d++) s += qf[d]*g_G[((size_t)bh*D_ + d)*D_ + e];
            out[((size_t)(b*L_ + l)*H_ + h)*D_ + e] += s/denom;
        }
    }
}

// ---------------- launch ----------------
extern "C" void kernel_launch(void* const* d_in, const int* in_sizes, int n_in,
                              void* d_out, int out_size) {
    const float* q  = (const float*)d_in[0];
    const float* k  = (const float*)d_in[1];
    const float* v  = (const float*)d_in[2];
    const float* w  = (const float*)d_in[3];
    const float* pb = (const float*)d_in[4];
    float* out = (float*)d_out;

    cudaFuncSetAttribute(attn_kernel, cudaFuncAttributeMaxDynamicSharedMemorySize, SMEM_BYTES);

    preproc1_kernel<<<2049, 256>>>(q, k, v, w);
    preproc2_kernel<<<1536, 256>>>(k, v);
    attn_kernel<<<BH_*NQB, 256, SMEM_BYTES>>>(out, pb);
    lin_dead_kernel<<<1, 256>>>(q, k, v, w, out);
}

// round 15
// speedup vs baseline: 1.0705x; 1.0705x over previous
#include <cuda_runtime.h>
#include <cuda_fp8.h>
#include <cuda_fp16.h>
#include <math.h>

#define B_    2
#define L_    2048
#define H_    16
#define D_    128
#define BH_   (B_*H_)      // 32
#define NQB   16
#define NKB   32
#define TOPK  16
#define SCALE_ 0.08838834764831845f   // 1/sqrt(128)
#define L2E_   1.4426950408889634f
#define FP8MAX_ (448.0f/2.25f)

// ---------------- scratch (device globals; no runtime allocation) ----------------
__device__ int    g_q8[BH_*L_*32];            // int8 packed, [bh][l][d/4]
__device__ int    g_k8[BH_*L_*32];
__device__ float  g_qsc[BH_*NQB];
__device__ float  g_ksc[BH_*NKB];
__device__ __half g_v16[(size_t)BH_*L_*D_];   // raw fp8 values as fp16, [bh][l][d]
__device__ float  g_qp[BH_*NQB*D_];
__device__ float  g_kp[BH_*NKB*D_];
__device__ float  g_vspart[BH_*16*D_];
__device__ float  g_vs[BH_*D_];
__device__ float  g_wflag[1];
// linear-branch scratch (dead unless proj_w != 0)
__device__ float g_qf[BH_*L_*D_];
__device__ float g_kf[BH_*L_*D_];
__device__ float g_ksum[BH_*D_];
__device__ float g_kvsum[BH_*D_*D_];
__device__ float g_G[BH_*D_*D_];

// ---------------- helpers ----------------
__device__ __forceinline__ void cpasync16(unsigned s, const void* g) {
    asm volatile("cp.async.cg.shared.global [%0], [%1], 16;\n" :: "r"(s), "l"(g));
}
#define CP_COMMIT() asm volatile("cp.async.commit_group;\n" ::: "memory")
#define CP_WAIT1()  asm volatile("cp.async.wait_group 1;\n" ::: "memory")

__device__ __forceinline__ void ldsm4(unsigned& r0, unsigned& r1, unsigned& r2, unsigned& r3,
                                      unsigned a) {
    asm volatile("ldmatrix.sync.aligned.m8n8.x4.shared.b16 {%0,%1,%2,%3}, [%4];"
                 : "=r"(r0), "=r"(r1), "=r"(r2), "=r"(r3) : "r"(a));
}
__device__ __forceinline__ void ldsm4t(unsigned& r0, unsigned& r1, unsigned& r2, unsigned& r3,
                                       unsigned a) {
    asm volatile("ldmatrix.sync.aligned.m8n8.x4.trans.shared.b16 {%0,%1,%2,%3}, [%4];"
                 : "=r"(r0), "=r"(r1), "=r"(r2), "=r"(r3) : "r"(a));
}
__device__ __forceinline__ void imma16832(int& c0, int& c1, int& c2, int& c3,
                                          unsigned a0, unsigned a1, unsigned a2, unsigned a3,
                                          unsigned b0, unsigned b1) {
    asm volatile("mma.sync.aligned.m16n8k32.row.col.s32.s8.s8.s32 "
                 "{%0,%1,%2,%3}, {%4,%5,%6,%7}, {%8,%9}, {%0,%1,%2,%3};"
                 : "+r"(c0), "+r"(c1), "+r"(c2), "+r"(c3)
                 : "r"(a0), "r"(a1), "r"(a2), "r"(a3), "r"(b0), "r"(b1));
}
__device__ __forceinline__ void hmma16816(float& d0, float& d1, float& d2, float& d3,
                                          unsigned a0, unsigned a1, unsigned a2, unsigned a3,
                                          unsigned b0, unsigned b1) {
    asm volatile("mma.sync.aligned.m16n8k16.row.col.f32.f16.f16.f32 "
                 "{%0,%1,%2,%3}, {%4,%5,%6,%7}, {%8,%9}, {%0,%1,%2,%3};"
                 : "+f"(d0), "+f"(d1), "+f"(d2), "+f"(d3)
                 : "r"(a0), "r"(a1), "r"(a2), "r"(a3), "r"(b0), "r"(b1));
}
__device__ __forceinline__ float ex2f(float x) {
    float r;
    asm("ex2.approx.f32 %0, %1;" : "=f"(r) : "f"(x));
    return r;
}

// round-to-nearest-even + saturating s8 pack of 4 scaled floats
__device__ __forceinline__ unsigned quantpack(float4 x, float inv) {
    int i0, i1, i2, i3;
    asm("cvt.rni.s32.f32 %0, %1;" : "=r"(i0) : "f"(x.x*inv));
    asm("cvt.rni.s32.f32 %0, %1;" : "=r"(i1) : "f"(x.y*inv));
    asm("cvt.rni.s32.f32 %0, %1;" : "=r"(i2) : "f"(x.z*inv));
    asm("cvt.rni.s32.f32 %0, %1;" : "=r"(i3) : "f"(x.w*inv));
    unsigned t, r;
    asm("cvt.pack.sat.s8.s32.b32 %0, %1, %2, %3;" : "=r"(t) : "r"(i3), "r"(i2), "r"(0u));
    asm("cvt.pack.sat.s8.s32.b32 %0, %1, %2, %3;" : "=r"(r) : "r"(i1), "r"(i0), "r"(t));
    return r;
}

// fp8-e4m3 satfinite roundtrip of 2 floats, result as packed half2 (low = x0)
__device__ __forceinline__ unsigned cvt2_fp8_f16(float x0, float x1) {
    unsigned short u;
    asm("cvt.rn.satfinite.e4m3x2.f32 %0, %1, %2;" : "=h"(u) : "f"(x1), "f"(x0));
    unsigned r;
    asm("cvt.rn.f16x2.e4m3x2 %0, %1;" : "=r"(r) : "h"(u));
    return r;
}

// ---------------- preproc1: fused_q | pool_k | vscale_part | wflag ----------------
__global__ void preproc1_kernel(const float* __restrict__ q, const float* __restrict__ k,
                                const float* __restrict__ v, const float* __restrict__ w) {
    __shared__ float red[256];
    __shared__ float sca[2];
    int tid = threadIdx.x;
    unsigned bx = blockIdx.x;
    if (bx < 512) {
        int bh = bx >> 4, qb = bx & 15;
        int b = bh >> 4, h = bh & 15;
        int d = tid & 127, half = tid >> 7;
        const float* base = q + ((size_t)(b*L_ + qb*128 + half*64)*H_ + h)*D_ + d;
        float s = 0.f, mx = 0.f;
#pragma unroll 8
        for (int r = 0; r < 64; r++) {
            float x = base[(size_t)r*H_*D_];
            s += x; mx = fmaxf(mx, fabsf(x));
        }
        red[tid] = mx; __syncthreads();
        for (int st = 128; st > 0; st >>= 1) { if (tid < st) red[tid] = fmaxf(red[tid], red[tid+st]); __syncthreads(); }
        if (tid == 0) { float sc = red[0]/127.f + 1e-8f; sca[0] = sc; sca[1] = 1.f/sc; g_qsc[bh*NQB + qb] = sc; }
        __syncthreads();
        red[tid] = s; __syncthreads();
        if (half == 0) g_qp[(bh*NQB + qb)*D_ + d] = (red[d] + red[d+128]) * (1.f/128.f);
        float inv = sca[1];
        for (int i4 = tid; i4 < 128*32; i4 += 256) {
            int r = i4 >> 5, c = i4 & 31;
            float4 x = *(const float4*)&q[((size_t)(b*L_ + qb*128 + r)*H_ + h)*D_ + 4*c];
            g_q8[(bh*L_ + qb*128 + r)*32 + c] = quantpack(x, inv);
        }
    } else if (bx < 1536) {
        int i = bx - 512;
        int bh = i >> 5, kb = i & 31;
        int b = bh >> 4, h = bh & 15;
        int d = tid & 127, half = tid >> 7;
        const float* base = k + ((size_t)(b*L_ + kb*64 + half*32)*H_ + h)*D_ + d;
        float s = 0.f;
#pragma unroll 8
        for (int r = 0; r < 32; r++) s += base[(size_t)r*H_*D_];
        red[tid] = s; __syncthreads();
        if (half == 0) g_kp[(bh*NKB + kb)*D_ + d] = (red[d] + red[d+128]) * (1.f/64.f);
    } else if (bx < 2048) {
        int i = bx - 1536;
        int bh = i >> 4, ch = i & 15;
        int b = bh >> 4, h = bh & 15;
        int d = tid & 127, half = tid >> 7;
        const float* base = v + ((size_t)(b*L_ + ch*128 + half*64)*H_ + h)*D_ + d;
        float mx = 0.f;
#pragma unroll 8
        for (int r = 0; r < 64; r++) mx = fmaxf(mx, fabsf(base[(size_t)r*H_*D_]));
        red[tid] = mx; __syncthreads();
        if (half == 0) g_vspart[(bh*16 + ch)*D_ + d] = fmaxf(red[d], red[d+128]);
    } else {
        float s = 0.f;
        for (int i = tid; i < D_*D_; i += 256) s += fabsf(w[i]);
        red[tid] = s; __syncthreads();
        for (int st = 128; st > 0; st >>= 1) { if (tid < st) red[tid] += red[tid+st]; __syncthreads(); }
        if (tid == 0) g_wflag[0] = red[0];
    }
}

// ---------------- preproc2: quant_k (km inline) | vdeq (fp8->fp16 stream) ----------
__global__ void preproc2_kernel(const float* __restrict__ k, const float* __restrict__ v) {
    __shared__ float red[256];
    __shared__ float svec[128];
    __shared__ float sca[2];
    int tid = threadIdx.x;
    unsigned bx = blockIdx.x;
    if (bx < 1024) {
        int bh = bx >> 5, kb = bx & 31;
        int b = bh >> 4, h = bh & 15;
        if (tid < 128) {
            // km = mean over key blocks of pooled k (matches pooled-mean numerics)
            float s = 0.f;
#pragma unroll
            for (int j = 0; j < NKB; j++) s += g_kp[(bh*NKB + j)*D_ + tid];
            svec[tid] = s * (1.f/NKB);
        }
        __syncthreads();
        int d = tid & 127, half = tid >> 7;
        const float* base = k + ((size_t)(b*L_ + kb*64 + half*32)*H_ + h)*D_ + d;
        float km = svec[d];
        float mx = 0.f;
#pragma unroll 8
        for (int r = 0; r < 32; r++) mx = fmaxf(mx, fabsf(base[(size_t)r*H_*D_] - km));
        red[tid] = mx; __syncthreads();
        for (int st = 128; st > 0; st >>= 1) { if (tid < st) red[tid] = fmaxf(red[tid], red[tid+st]); __syncthreads(); }
        if (tid == 0) { float sc = red[0]/127.f + 1e-8f; g_ksc[bh*NKB + kb] = sc; sca[1] = 1.f/sc; }
        __syncthreads();
        float inv = sca[1];
        for (int i4 = tid; i4 < 64*32; i4 += 256) {
            int r = i4 >> 5, c = i4 & 31;
            float4 x = *(const float4*)&k[((size_t)(b*L_ + kb*64 + r)*H_ + h)*D_ + 4*c];
            x.x -= svec[4*c+0]; x.y -= svec[4*c+1]; x.z -= svec[4*c+2]; x.w -= svec[4*c+3];
            g_k8[(bh*L_ + kb*64 + r)*32 + c] = quantpack(x, inv);
        }
    } else {
        int i = bx - 1024;
        int bh = i >> 4, lc = i & 15;
        int b = bh >> 4, h = bh & 15;
        if (tid < 128) {
            float mx = 0.f;
#pragma unroll
            for (int ch = 0; ch < 16; ch++) mx = fmaxf(mx, g_vspart[(bh*16 + ch)*D_ + tid]);
            float s = mx/FP8MAX_ + 1e-8f;
            g_vs[bh*D_ + tid] = s;            // idempotent across lc blocks
            svec[tid] = 1.f/s;
        }
        __syncthreads();
        int l0 = lc*128;
        for (int i4 = tid; i4 < 128*32; i4 += 256) {
            int r = i4 >> 5, d4 = (i4 & 31) << 2;
            float4 x = *(const float4*)&v[((size_t)(b*L_ + l0 + r)*H_ + h)*D_ + d4];
            uint2 u;
            u.x = cvt2_fp8_f16(x.x*svec[d4+0], x.y*svec[d4+1]);
            u.y = cvt2_fp8_f16(x.z*svec[d4+2], x.w*svec[d4+3]);
            *(uint2*)(g_v16 + ((size_t)(bh*L_ + l0 + r))*D_ + d4) = u;
        }
    }
}

// ---------------- flash block-sparse attention: IMMA S + HMMA PV ----------------
// smem: [0..1023] sim(32f)+sel(16i) | sQ 128x144B | sK[3] 64x144B | sV[3] 64x272B
#define SQ_OFF  1024
#define SK_OFF(st) (19456 + (st)*9216)
#define SV_OFF(st) (47104 + (st)*17408)
#define SMEM_BYTES 99328

__global__ void __launch_bounds__(256, 2) attn_kernel(float* __restrict__ out,
                                                      const float* __restrict__ pb) {
    extern __shared__ char sm[];
    unsigned sbase = (unsigned)__cvta_generic_to_shared(sm);
    float* simS = (float*)sm;
    int*   selS = (int*)(sm + 128);

    int bh = blockIdx.x >> 4, qb = blockIdx.x & 15;
    int b = bh >> 4, h = bh & 15;
    int tid = threadIdx.x;
    int w = tid >> 5, lane = tid & 31;
    int g = lane >> 2, tig = lane & 3;
    int lr = lane & 7, lm = lane >> 3;

    unsigned qmat = sbase + SQ_OFF + (unsigned)((16*w + 8*(lm & 1) + lr)*144 + 16*(lm >> 1));
    unsigned bmat = (unsigned)((8*(lm >> 1) + lr)*144 + 16*(lm & 1));
    unsigned vmat = (unsigned)(((lm & 1)*8 + lr)*272 + (lm >> 1)*16);

    float qs = g_qsc[bh*NQB + qb];
    const float* kscp = g_ksc + bh*NKB;

    // ---- group 0: Q prefetch (overlaps with sim/topk) ----
    {
        const char* qg = (const char*)(g_q8 + (bh*L_ + qb*128)*32);
        for (int c = tid; c < 1024; c += 256) {
            int r = c >> 3, c8 = c & 7;
            cpasync16(sbase + SQ_OFF + r*144 + c8*16, qg + r*128 + c8*16);
        }
        CP_COMMIT();
    }

    // ---- inline block-similarity + stable top-k ----
    {
        int ki = tid >> 3, part = tid & 7;
        const float* qp = g_qp + (bh*NQB + qb)*D_;
        const float* kp = g_kp + (bh*NKB + ki)*D_;
        int d0 = part*16;
        float s = 0.f;
#pragma unroll
        for (int j = 0; j < 16; j++) s += qp[d0+j]*kp[d0+j];
        s += __shfl_xor_sync(0xffffffffu, s, 1);
        s += __shfl_xor_sync(0xffffffffu, s, 2);
        s += __shfl_xor_sync(0xffffffffu, s, 4);
        if (part == 0) simS[ki] = s;
    }
    __syncthreads();
    if (tid < 32) {
        float sj = simS[tid];
        int rank = 0;
#pragma unroll
        for (int i = 0; i < 32; i++)
            rank += (simS[i] > sj) || (simS[i] == sj && i < tid);
        if (rank < TOPK) selS[rank] = tid;
    }
    __syncthreads();

    // ---- groups 1,2: prefetch stages 0 and 1 ----
#pragma unroll
    for (int ps = 0; ps < 2; ps++) {
        int kb = selS[ps];
        const char* kg = (const char*)(g_k8 + (bh*L_ + kb*64)*32);
        for (int c = tid; c < 512; c += 256) {
            int r = c >> 3, c8 = c & 7;
            cpasync16(sbase + SK_OFF(ps) + r*144 + c8*16, kg + r*128 + c8*16);
        }
        for (int c = tid; c < 1024; c += 256) {
            int r = c >> 4, c16 = c & 15;
            cpasync16(sbase + SV_OFF(ps) + r*272 + c16*16,
                      (const char*)(g_v16 + ((size_t)(bh*L_ + kb*64 + r))*D_) + c16*16);
        }
        CP_COMMIT();
    }

    float o[16][4];
    float m0 = -INFINITY, m1 = -INFINITY, l0 = 0.f, l1 = 0.f;
#pragma unroll
    for (int dt = 0; dt < 16; dt++)
#pragma unroll
        for (int e = 0; e < 4; e++) o[dt][e] = 0.f;

    for (int s = 0; s < TOPK; s++) {
        int st = s - (s/3)*3;
        CP_WAIT1();
        __syncthreads();          // single barrier: visibility + ring protection

        if (s + 2 < TOPK) {       // prefetch stage s+2 (writes the stage read in iter s-1)
            int kbn = selS[s+2];
            int nst = (s+2) - ((s+2)/3)*3;
            const char* kg = (const char*)(g_k8 + (bh*L_ + kbn*64)*32);
            for (int c = tid; c < 512; c += 256) {
                int r = c >> 3, c8 = c & 7;
                cpasync16(sbase + SK_OFF(nst) + r*144 + c8*16, kg + r*128 + c8*16);
            }
            for (int c = tid; c < 1024; c += 256) {
                int r = c >> 4, c16 = c & 15;
                cpasync16(sbase + SV_OFF(nst) + r*272 + c16*16,
                          (const char*)(g_v16 + ((size_t)(bh*L_ + kbn*64 + r))*D_) + c16*16);
            }
        }
        CP_COMMIT();

        float csc2 = qs * kscp[selS[s]] * (SCALE_ * L2E_);   // log2-domain scale
        unsigned skb = sbase + SK_OFF(st) + bmat;
        unsigned svb = sbase + SV_OFF(st) + vmat;

        // ---- S = Q K^T (IMMA) ----
        int c[8][4];
#pragma unroll
        for (int nt = 0; nt < 8; nt++)
#pragma unroll
            for (int e = 0; e < 4; e++) c[nt][e] = 0;

#pragma unroll
        for (int ks = 0; ks < 4; ks++) {
            unsigned a0, a1, a2, a3;
            ldsm4(a0, a1, a2, a3, qmat + 32*ks);
#pragma unroll
            for (int p = 0; p < 4; p++) {
                unsigned b0, b1, b2, b3;
                ldsm4(b0, b1, b2, b3, skb + p*(16*144) + 32*ks);
                imma16832(c[2*p][0], c[2*p][1], c[2*p][2], c[2*p][3],
                          a0, a1, a2, a3, b0, b1);
                imma16832(c[2*p+1][0], c[2*p+1][1], c[2*p+1][2], c[2*p+1][3],
                          a0, a1, a2, a3, b2, b3);
            }
        }

        // ---- online softmax (log2 domain, ex2) ----
        float sv[8][4];
        float mloc0 = -INFINITY, mloc1 = -INFINITY;
#pragma unroll
        for (int nt = 0; nt < 8; nt++) {
            sv[nt][0] = (float)c[nt][0] * csc2;
            sv[nt][1] = (float)c[nt][1] * csc2;
            sv[nt][2] = (float)c[nt][2] * csc2;
            sv[nt][3] = (float)c[nt][3] * csc2;
            mloc0 = fmaxf(mloc0, fmaxf(sv[nt][0], sv[nt][1]));
            mloc1 = fmaxf(mloc1, fmaxf(sv[nt][2], sv[nt][3]));
        }
        mloc0 = fmaxf(mloc0, __shfl_xor_sync(0xffffffffu, mloc0, 1));
        mloc0 = fmaxf(mloc0, __shfl_xor_sync(0xffffffffu, mloc0, 2));
        mloc1 = fmaxf(mloc1, __shfl_xor_sync(0xffffffffu, mloc1, 1));
        mloc1 = fmaxf(mloc1, __shfl_xor_sync(0xffffffffu, mloc1, 2));
        float mn0 = fmaxf(m0, mloc0), mn1 = fmaxf(m1, mloc1);
        float corr0 = ex2f(m0 - mn0), corr1 = ex2f(m1 - mn1);
        m0 = mn0; m1 = mn1;

        unsigned ph0[8], ph1[8];
        float ps0 = 0.f, ps1 = 0.f;
#pragma unroll
        for (int nt = 0; nt < 8; nt++) {
            float p00 = ex2f(sv[nt][0] - mn0), p01 = ex2f(sv[nt][1] - mn0);
            __half2 h0 = __floats2half2_rn(p00, p01);
            ph0[nt] = *reinterpret_cast<unsigned*>(&h0);
            float2 f0 = __half22float2(h0);
            ps0 += f0.x + f0.y;
            float p10 = ex2f(sv[nt][2] - mn1), p11 = ex2f(sv[nt][3] - mn1);
            __half2 h1 = __floats2half2_rn(p10, p11);
            ph1[nt] = *reinterpret_cast<unsigned*>(&h1);
            float2 f1 = __half22float2(h1);
            ps1 += f1.x + f1.y;
        }
        ps0 += __shfl_xor_sync(0xffffffffu, ps0, 1);
        ps0 += __shfl_xor_sync(0xffffffffu, ps0, 2);
        ps1 += __shfl_xor_sync(0xffffffffu, ps1, 1);
        ps1 += __shfl_xor_sync(0xffffffffu, ps1, 2);
        l0 = l0*corr0 + ps0;
        l1 = l1*corr1 + ps1;

#pragma unroll
        for (int dt = 0; dt < 16; dt++) {
            o[dt][0] *= corr0; o[dt][1] *= corr0;
            o[dt][2] *= corr1; o[dt][3] *= corr1;
        }

        // ---- O += P V (HMMA, V fragments via ldmatrix.trans on [l][d]) ----
#pragma unroll
        for (int kc = 0; kc < 4; kc++) {
            unsigned pa0 = ph0[2*kc],   pa1 = ph1[2*kc];
            unsigned pa2 = ph0[2*kc+1], pa3 = ph1[2*kc+1];
#pragma unroll
            for (int p = 0; p < 8; p++) {
                unsigned b0, b1, b2, b3;
                ldsm4t(b0, b1, b2, b3, svb + kc*(16*272) + p*32);
                hmma16816(o[2*p][0], o[2*p][1], o[2*p][2], o[2*p][3],
                          pa0, pa1, pa2, pa3, b0, b1);
                hmma16816(o[2*p+1][0], o[2*p+1][1], o[2*p+1][2], o[2*p+1][3],
                          pa0, pa1, pa2, pa3, b2, b3);
            }
        }
    }

    // ---- epilogue ----
    float inv0 = 1.f / l0, inv1 = 1.f / l1;
    int row0 = qb*128 + 16*w + g, row1 = row0 + 8;
    float* o0 = out + ((size_t)(b*L_ + row0)*H_ + h)*D_;
    float* o1 = out + ((size_t)(b*L_ + row1)*H_ + h)*D_;
    const float* vs = g_vs + bh*D_;
#pragma unroll
    for (int dt = 0; dt < 16; dt++) {
        int d0 = 8*dt + 2*tig;
        float2 vsc = *(const float2*)&vs[d0];
        float2 bb  = *(const float2*)&pb[d0];
        float2 r0, r1;
        r0.x = o[dt][0]*vsc.x*inv0 + bb.x;
        r0.y = o[dt][1]*vsc.y*inv0 + bb.y;
        r1.x = o[dt][2]*vsc.x*inv1 + bb.x;
        r1.y = o[dt][3]*vsc.y*inv1 + bb.y;
        *(float2*)&o0[d0] = r0;
        *(float2*)&o1[d0] = r1;
    }
}

// ---------------- linear branch, single guarded kernel (dead when proj_w == 0) --
__global__ void lin_dead_kernel(const float* __restrict__ q, const float* __restrict__ k,
                                const float* __restrict__ v, const float* __restrict__ w,
                                float* __restrict__ out) {
    if (g_wflag[0] == 0.f) return;
    int tid = threadIdx.x;
    for (int row = tid; row < 2*BH_*L_; row += 256) {
        int which = row >= BH_*L_;
        int rr = which ? row - BH_*L_ : row;
        int bh = rr / L_, l = rr % L_;
        int b = bh >> 4, h = bh & 15;
        const float* src = (which ? k : q) + ((size_t)(b*L_ + l)*H_ + h)*D_;
        float mx = -INFINITY;
        for (int d = 0; d < D_; d++) mx = fmaxf(mx, src[d]);
        float sum = 0.f;
        float* dst = (which ? g_kf : g_qf) + (size_t)(bh*L_ + l)*D_;
        for (int d = 0; d < D_; d++) { float e = __expf(src[d]-mx); dst[d] = e; sum += e; }
        float inv = 1.f/sum;
        for (int d = 0; d < D_; d++) dst[d] *= inv;
    }
    __syncthreads();
    for (int i = tid; i < BH_*D_; i += 256) {
        int bh = i >> 7;
        float s = 0.f;
        for (int l = 0; l < L_; l++) s += g_kf[(size_t)(bh*L_ + l)*D_ + (i & 127)];
        g_ksum[i] = s;
    }
    __syncthreads();
    for (int i = tid; i < BH_*D_*D_; i += 256) {
        int bh = i >> 14, rem = i & 16383, d = rem >> 7, e = rem & 127;
        int b = bh >> 4, h = bh & 15;
        float s = 0.f;
        for (int l = 0; l < L_; l++)
            s += g_kf[(size_t)(bh*L_ + l)*D_ + d] * v[((size_t)(b*L_ + l)*H_ + h)*D_ + e];
        g_kvsum[i] = s;
    }
    __syncthreads();
    for (int i = tid; i < BH_*D_*D_; i += 256) {
        int bh = i >> 14, rem = i & 16383, d = rem >> 7, e = rem & 127;
        float s = 0.f;
        for (int f = 0; f < D_; f++) s += g_kvsum[((size_t)bh*D_ + d)*D_ + f]*w[e*D_ + f];
        g_G[i] = s;
    }
    __syncthreads();
    for (int i = tid; i < BH_*L_; i += 256) {
        int bh = i / L_, l = i % L_;
        int b = bh >> 4, h = bh & 15;
        const float* qf = g_qf + (size_t)(bh*L_ + l)*D_;
        float pd = 0.f;
        for (int d = 0; d < D_; d++) pd += qf[d]*g_ksum[bh*D_ + d];
        float denom = 1e-5f + pd;
        for (int e = 0; e < D_; e++) {
            float s = 0.f;
            for (int d = 0; d < D_; d++) s += qf[d]*g_G[((size_t)bh*D_ + d)*D_ + e];
            out[((size_t)(b*L_ + l)*H_ + h)*D_ + e] += s/denom;
        }
    }
}

// ---------------- launch ----------------
extern "C" void kernel_launch(void* const* d_in, const int* in_sizes, int n_in,
                              void* d_out, int out_size) {
    const float* q  = (const float*)d_in[0];
    const float* k  = (const float*)d_in[1];
    const float* v  = (const float*)d_in[2];
    const float* w  = (const float*)d_in[3];
    const float* pb = (const float*)d_in[4];
    float* out = (float*)d_out;

    cudaFuncSetAttribute(attn_kernel, cudaFuncAttributeMaxDynamicSharedMemorySize, SMEM_BYTES);

    preproc1_kernel<<<2049, 256>>>(q, k, v, w);
    preproc2_kernel<<<1536, 256>>>(k, v);
    attn_kernel<<<BH_*NQB, 256, SMEM_BYTES>>>(out, pb);
    lin_dead_kernel<<<1, 256>>>(q, k, v, w, out);
}